// round 4
// baseline (speedup 1.0000x reference)
#include <cuda_runtime.h>
#include <cuda_bf16.h>
#include <cstdint>

// Problem constants
#define BATCH 16
#define CCH   256        // channels
#define NPOS  1024       // H*W
#define NH    4
#define DH    64
#define GRP   8
#define CPG   32         // channels per group

typedef unsigned long long ull;

// ---------------------------------------------------------------------------
// Scratch (device globals; allocation is forbidden)
// ---------------------------------------------------------------------------
__device__ float g_xn [BATCH * CCH    * NPOS];   // 16 MB  group-normed x
__device__ float g_qkv[BATCH * 3*CCH  * NPOS];   // 48 MB  qkv projections
__device__ float g_o  [BATCH * CCH    * NPOS];   // 16 MB  attention output

// ---------------------------------------------------------------------------
// f32x2 helpers (sm_103a packed fp32 FMA — SASS FFMA2, PTX-only path)
// ---------------------------------------------------------------------------
__device__ __forceinline__ ull fma2(ull a, ull b, ull c) {
    ull d;
    asm("fma.rn.f32x2 %0, %1, %2, %3;" : "=l"(d) : "l"(a), "l"(b), "l"(c));
    return d;
}
__device__ __forceinline__ ull pack2(float x, float y) {
    union { float2 f; ull u; } t; t.f = make_float2(x, y); return t.u;
}
__device__ __forceinline__ ull packbb(float x) { return pack2(x, x); }
__device__ __forceinline__ float2 unpack2(ull u) {
    union { float2 f; ull u; } t; t.u = u; return t.f;
}

// ---------------------------------------------------------------------------
// Kernel 1: GroupNorm.  One block per (b, g); 32768 elems per group.
// ---------------------------------------------------------------------------
__global__ __launch_bounds__(256)
void gn_kernel(const float* __restrict__ x,
               const float* __restrict__ w,
               const float* __restrict__ bia) {
    const int blk = blockIdx.x;
    const int b = blk >> 3, g = blk & 7;
    const size_t base = ((size_t)b * CCH + (size_t)g * CPG) * NPOS;
    const float4* xp = (const float4*)(x + base);
    float4* op = (float4*)(g_xn + base);
    const int tid = threadIdx.x;

    float s = 0.f, ss = 0.f;
    #pragma unroll 8
    for (int it = 0; it < 32; ++it) {
        float4 v = xp[it * 256 + tid];
        s  += v.x + v.y + v.z + v.w;
        ss += v.x*v.x + v.y*v.y + v.z*v.z + v.w*v.w;
    }
    __shared__ float rs[256], rq[256];
    rs[tid] = s; rq[tid] = ss;
    __syncthreads();
    for (int st = 128; st > 0; st >>= 1) {
        if (tid < st) { rs[tid] += rs[tid + st]; rq[tid] += rq[tid + st]; }
        __syncthreads();
    }
    __shared__ float csc[CPG], csh[CPG];
    if (tid < CPG) {
        const float invM = 1.f / 32768.f;
        float mean = rs[0] * invM;
        float var  = rq[0] * invM - mean * mean;
        float inv  = rsqrtf(var + 1e-5f);
        int c = g * CPG + tid;
        float sc = w[c] * inv;
        csc[tid] = sc;
        csh[tid] = bia[c] - mean * sc;
    }
    __syncthreads();
    #pragma unroll 8
    for (int it = 0; it < 32; ++it) {
        int idx = it * 256 + tid;
        int ch = idx >> 8;                  // 256 float4 per channel
        float4 v = xp[idx];
        float a = csc[ch], t = csh[ch];
        v.x = v.x * a + t;  v.y = v.y * a + t;
        v.z = v.z * a + t;  v.w = v.w * a + t;
        op[idx] = v;
    }
}

// ---------------------------------------------------------------------------
// Kernel 2: batched GEMM  out[b,m,n] = sum_c W[m,c]*X[b,c,n] + bias[m] (+res)
// BM=64 BN=128 BK=16, 256 threads, per-thread 4x8 tile via FFMA2.
// phase 0: X = g_xn, out = g_qkv (M=768).  phase 1: X = g_o, out = ext (M=256).
// ---------------------------------------------------------------------------
__global__ __launch_bounds__(256)
void gemm_kernel(const float* __restrict__ W,
                 const float* __restrict__ bias,
                 const float* __restrict__ res,   // nullptr or residual [B,M,N]
                 float* __restrict__ out_ext,
                 int M, int phase) {
    const int Kd = CCH;            // 256
    const int Nd = NPOS;           // 1024
    const float* X  = (phase == 0) ? g_xn  : g_o;
    float*       out = (phase == 0) ? g_qkv : out_ext;

    const int bx = blockIdx.x;     // n tile (8)
    const int by = blockIdx.y;     // m tile
    const int b  = blockIdx.z;
    const int tid = threadIdx.x;
    const int tx = tid & 15, ty = tid >> 4;

    __shared__ __align__(16) float Ws[16][64];
    __shared__ __align__(16) float Xs[16][128];

    const float* Xb = X + (size_t)b * Kd * Nd;
    const int m0 = by * 64, n0 = bx * 128;

    ull acc[4][4];
    #pragma unroll
    for (int i = 0; i < 4; ++i)
        #pragma unroll
        for (int j = 0; j < 4; ++j) acc[i][j] = 0ull;

    const int wrow = tid >> 2;            // 0..63
    const int wk4  = (tid & 3) * 4;
    const int s0 = tid, s1 = tid + 256;   // X float4 slots

    for (int k0 = 0; k0 < Kd; k0 += 16) {
        float4 wv  = *(const float4*)(W + (size_t)(m0 + wrow) * Kd + k0 + wk4);
        float4 xv0 = *(const float4*)(Xb + (size_t)(k0 + (s0 >> 5)) * Nd + n0 + (s0 & 31) * 4);
        float4 xv1 = *(const float4*)(Xb + (size_t)(k0 + (s1 >> 5)) * Nd + n0 + (s1 & 31) * 4);
        __syncthreads();
        Ws[wk4 + 0][wrow] = wv.x; Ws[wk4 + 1][wrow] = wv.y;
        Ws[wk4 + 2][wrow] = wv.z; Ws[wk4 + 3][wrow] = wv.w;
        *(float4*)&Xs[s0 >> 5][(s0 & 31) * 4] = xv0;
        *(float4*)&Xs[s1 >> 5][(s1 & 31) * 4] = xv1;
        __syncthreads();

        #pragma unroll
        for (int kk = 0; kk < 16; ++kk) {
            float4 a4 = *(const float4*)&Ws[kk][ty * 4];
            ull am[4] = { packbb(a4.x), packbb(a4.y), packbb(a4.z), packbb(a4.w) };
            ulonglong2 b0 = *(const ulonglong2*)&Xs[kk][tx * 8];
            ulonglong2 b1 = *(const ulonglong2*)&Xs[kk][tx * 8 + 4];
            ull bn[4] = { b0.x, b0.y, b1.x, b1.y };
            #pragma unroll
            for (int i = 0; i < 4; ++i)
                #pragma unroll
                for (int j = 0; j < 4; ++j)
                    acc[i][j] = fma2(am[i], bn[j], acc[i][j]);
        }
    }

    // epilogue
    #pragma unroll
    for (int i = 0; i < 4; ++i) {
        const int m = m0 + ty * 4 + i;
        const float bv = bias[m];
        float r[8];
        #pragma unroll
        for (int j = 0; j < 4; ++j) {
            float2 f = unpack2(acc[i][j]);
            r[2*j]   = f.x + bv;
            r[2*j+1] = f.y + bv;
        }
        const size_t obase = ((size_t)b * M + m) * Nd + n0 + tx * 8;
        if (res) {
            float4 r0 = *(const float4*)(res + obase);
            float4 r1 = *(const float4*)(res + obase + 4);
            r[0] += r0.x; r[1] += r0.y; r[2] += r0.z; r[3] += r0.w;
            r[4] += r1.x; r[5] += r1.y; r[6] += r1.z; r[7] += r1.w;
        }
        *(float4*)(out + obase)     = make_float4(r[0], r[1], r[2], r[3]);
        *(float4*)(out + obase + 4) = make_float4(r[4], r[5], r[6], r[7]);
    }
}

// ---------------------------------------------------------------------------
// Kernel 3: flash attention.  One thread = one query.
// grid (8 qtiles, NH, B), 128 threads.  K/V tiles of TJ=64 in SMEM [c][j].
// ---------------------------------------------------------------------------
__global__ __launch_bounds__(128, 1)
void attn_kernel() {
    const int b = blockIdx.z, h = blockIdx.y;
    const int tid = threadIdx.x;
    const int i = blockIdx.x * 128 + tid;   // query position, < 1024

    const float* qb = g_qkv + ((size_t)b * 3 * CCH + (size_t)h * DH) * NPOS;
    const float* kb = qb + (size_t)CCH * NPOS;
    const float* vb = qb + (size_t)2 * CCH * NPOS;

    __shared__ __align__(16) float ks[DH][64];
    __shared__ __align__(16) float vs[DH][64];

    float q[DH];
    #pragma unroll
    for (int c = 0; c < DH; ++c) q[c] = qb[(size_t)c * NPOS + i] * 0.125f; // dh^-0.5

    float o[DH];
    #pragma unroll
    for (int c = 0; c < DH; ++c) o[c] = 0.f;

    float mrun = -1e30f, lrun = 0.f;
    ull sp[32];

    for (int jt = 0; jt < 16; ++jt) {
        const float* kt = kb + jt * 64;
        const float* vt = vb + jt * 64;
        __syncthreads();   // protect prior tile reads
        #pragma unroll 4
        for (int r = 0; r < 32; ++r) {
            int lin = r * 128 + tid;
            int c = lin >> 6, j = lin & 63;
            ks[c][j] = kt[(size_t)c * NPOS + j];
            vs[c][j] = vt[(size_t)c * NPOS + j];
        }
        __syncthreads();

        // --- scores: sp[p] accumulates (s_{2p}, s_{2p+1}) over c ---
        #pragma unroll
        for (int p = 0; p < 32; ++p) sp[p] = 0ull;
        #pragma unroll
        for (int c = 0; c < DH; ++c) {
            ull qq = packbb(q[c]);
            const ulonglong2* kr = (const ulonglong2*)&ks[c][0];
            #pragma unroll
            for (int p4 = 0; p4 < 16; ++p4) {
                ulonglong2 kv = kr[p4];        // broadcast LDS.128
                sp[2*p4]   = fma2(qq, kv.x, sp[2*p4]);
                sp[2*p4+1] = fma2(qq, kv.y, sp[2*p4+1]);
            }
        }

        // --- online softmax ---
        float mt = mrun;
        #pragma unroll
        for (int p = 0; p < 32; ++p) {
            float2 f = unpack2(sp[p]);
            mt = fmaxf(mt, fmaxf(f.x, f.y));
        }
        float alpha = __expf(mrun - mt);
        mrun = mt;
        float esum = 0.f;
        #pragma unroll
        for (int p = 0; p < 32; ++p) {
            float2 f = unpack2(sp[p]);
            float el = __expf(f.x - mt);
            float eh = __expf(f.y - mt);
            esum += el + eh;
            sp[p] = pack2(el, eh);
        }
        lrun = lrun * alpha + esum;

        // --- o[c] = o[c]*alpha + sum_j p[j] * v[c][j] ---
        #pragma unroll
        for (int c = 0; c < DH; ++c) {
            ull acc = 0ull;
            const ulonglong2* vr = (const ulonglong2*)&vs[c][0];
            #pragma unroll
            for (int p4 = 0; p4 < 16; ++p4) {
                ulonglong2 vv = vr[p4];        // broadcast LDS.128
                acc = fma2(sp[2*p4],   vv.x, acc);
                acc = fma2(sp[2*p4+1], vv.y, acc);
            }
            float2 f = unpack2(acc);
            o[c] = o[c] * alpha + (f.x + f.y);
        }
    }

    const float inv = 1.f / lrun;
    float* ob = g_o + ((size_t)b * CCH + (size_t)h * DH) * NPOS;
    #pragma unroll
    for (int c = 0; c < DH; ++c)
        ob[(size_t)c * NPOS + i] = o[c] * inv;
}

// ---------------------------------------------------------------------------
// Launch
// ---------------------------------------------------------------------------
extern "C" void kernel_launch(void* const* d_in, const int* in_sizes, int n_in,
                              void* d_out, int out_size) {
    const float* x        = (const float*)d_in[0];
    const float* n_weight = (const float*)d_in[1];
    const float* n_bias   = (const float*)d_in[2];
    const float* qkv_w    = (const float*)d_in[3];
    const float* qkv_b    = (const float*)d_in[4];
    const float* p_w      = (const float*)d_in[5];
    const float* p_b      = (const float*)d_in[6];
    float* out = (float*)d_out;

    // 1) GroupNorm -> g_xn
    gn_kernel<<<BATCH * GRP, 256>>>(x, n_weight, n_bias);

    // 2) QKV GEMM: g_qkv[b,o,n] = qkv_w @ g_xn + qkv_b   (M=768)
    gemm_kernel<<<dim3(8, 12, BATCH), 256>>>(qkv_w, qkv_b, nullptr, nullptr, 768, 0);

    // 3) Attention: g_qkv -> g_o
    attn_kernel<<<dim3(8, NH, BATCH), 128>>>();

    // 4) Proj + bias + residual: out = x + p_w @ g_o + p_b   (M=256)
    gemm_kernel<<<dim3(8, 4, BATCH), 256>>>(p_w, p_b, x, out, 256, 1);
}

// round 5
// speedup vs baseline: 1.7874x; 1.7874x over previous
#include <cuda_runtime.h>
#include <cuda_bf16.h>
#include <cstdint>

// Problem constants
#define BATCH 16
#define CCH   256        // channels
#define NPOS  1024       // H*W
#define NH    4
#define DH    64
#define GRP   8
#define CPG   32         // channels per group

typedef unsigned long long ull;

// ---------------------------------------------------------------------------
// Scratch (device globals; allocation is forbidden)
// ---------------------------------------------------------------------------
__device__ float g_xn [BATCH * CCH    * NPOS];   // 16 MB  group-normed x
__device__ float g_qkv[BATCH * 3*CCH  * NPOS];   // 48 MB  qkv projections
__device__ float g_o  [BATCH * CCH    * NPOS];   // 16 MB  attention output

// ---------------------------------------------------------------------------
// f32x2 helpers (sm_103a packed fp32 FMA — SASS FFMA2, PTX-only path)
// ---------------------------------------------------------------------------
__device__ __forceinline__ ull fma2(ull a, ull b, ull c) {
    ull d;
    asm("fma.rn.f32x2 %0, %1, %2, %3;" : "=l"(d) : "l"(a), "l"(b), "l"(c));
    return d;
}
__device__ __forceinline__ ull mul2(ull a, ull b) {
    ull d;
    asm("mul.rn.f32x2 %0, %1, %2;" : "=l"(d) : "l"(a), "l"(b));
    return d;
}
__device__ __forceinline__ ull pack2(float x, float y) {
    union { float2 f; ull u; } t; t.f = make_float2(x, y); return t.u;
}
__device__ __forceinline__ ull packbb(float x) { return pack2(x, x); }
__device__ __forceinline__ float2 unpack2(ull u) {
    union { float2 f; ull u; } t; t.u = u; return t.f;
}

// ---------------------------------------------------------------------------
// Kernel 1: GroupNorm.  One block per (b, g); 32768 elems per group.
// ---------------------------------------------------------------------------
__global__ __launch_bounds__(256)
void gn_kernel(const float* __restrict__ x,
               const float* __restrict__ w,
               const float* __restrict__ bia) {
    const int blk = blockIdx.x;
    const int b = blk >> 3, g = blk & 7;
    const size_t base = ((size_t)b * CCH + (size_t)g * CPG) * NPOS;
    const float4* xp = (const float4*)(x + base);
    float4* op = (float4*)(g_xn + base);
    const int tid = threadIdx.x;

    float s = 0.f, ss = 0.f;
    #pragma unroll 8
    for (int it = 0; it < 32; ++it) {
        float4 v = xp[it * 256 + tid];
        s  += v.x + v.y + v.z + v.w;
        ss += v.x*v.x + v.y*v.y + v.z*v.z + v.w*v.w;
    }
    __shared__ float rs[256], rq[256];
    rs[tid] = s; rq[tid] = ss;
    __syncthreads();
    for (int st = 128; st > 0; st >>= 1) {
        if (tid < st) { rs[tid] += rs[tid + st]; rq[tid] += rq[tid + st]; }
        __syncthreads();
    }
    __shared__ float csc[CPG], csh[CPG];
    if (tid < CPG) {
        const float invM = 1.f / 32768.f;
        float mean = rs[0] * invM;
        float var  = rq[0] * invM - mean * mean;
        float inv  = rsqrtf(var + 1e-5f);
        int c = g * CPG + tid;
        float sc = w[c] * inv;
        csc[tid] = sc;
        csh[tid] = bia[c] - mean * sc;
    }
    __syncthreads();
    #pragma unroll 8
    for (int it = 0; it < 32; ++it) {
        int idx = it * 256 + tid;
        int ch = idx >> 8;                  // 256 float4 per channel
        float4 v = xp[idx];
        float a = csc[ch], t = csh[ch];
        v.x = v.x * a + t;  v.y = v.y * a + t;
        v.z = v.z * a + t;  v.w = v.w * a + t;
        op[idx] = v;
    }
}

// ---------------------------------------------------------------------------
// Kernel 2: batched GEMM  out[b,m,n] = sum_c W[m,c]*X[b,c,n] + bias[m] (+res)
// BM=64 BN=128 BK=16, 256 threads, per-thread 4x8 tile via FFMA2.
// ---------------------------------------------------------------------------
__global__ __launch_bounds__(256)
void gemm_kernel(const float* __restrict__ W,
                 const float* __restrict__ bias,
                 const float* __restrict__ res,
                 float* __restrict__ out_ext,
                 int M, int phase) {
    const int Kd = CCH;
    const int Nd = NPOS;
    const float* X  = (phase == 0) ? g_xn  : g_o;
    float*       out = (phase == 0) ? g_qkv : out_ext;

    const int bx = blockIdx.x;
    const int by = blockIdx.y;
    const int b  = blockIdx.z;
    const int tid = threadIdx.x;
    const int tx = tid & 15, ty = tid >> 4;

    __shared__ __align__(16) float Ws[16][64];
    __shared__ __align__(16) float Xs[16][128];

    const float* Xb = X + (size_t)b * Kd * Nd;
    const int m0 = by * 64, n0 = bx * 128;

    ull acc[4][4];
    #pragma unroll
    for (int i = 0; i < 4; ++i)
        #pragma unroll
        for (int j = 0; j < 4; ++j) acc[i][j] = 0ull;

    const int wrow = tid >> 2;
    const int wk4  = (tid & 3) * 4;
    const int s0 = tid, s1 = tid + 256;

    for (int k0 = 0; k0 < Kd; k0 += 16) {
        float4 wv  = *(const float4*)(W + (size_t)(m0 + wrow) * Kd + k0 + wk4);
        float4 xv0 = *(const float4*)(Xb + (size_t)(k0 + (s0 >> 5)) * Nd + n0 + (s0 & 31) * 4);
        float4 xv1 = *(const float4*)(Xb + (size_t)(k0 + (s1 >> 5)) * Nd + n0 + (s1 & 31) * 4);
        __syncthreads();
        Ws[wk4 + 0][wrow] = wv.x; Ws[wk4 + 1][wrow] = wv.y;
        Ws[wk4 + 2][wrow] = wv.z; Ws[wk4 + 3][wrow] = wv.w;
        *(float4*)&Xs[s0 >> 5][(s0 & 31) * 4] = xv0;
        *(float4*)&Xs[s1 >> 5][(s1 & 31) * 4] = xv1;
        __syncthreads();

        #pragma unroll
        for (int kk = 0; kk < 16; ++kk) {
            float4 a4 = *(const float4*)&Ws[kk][ty * 4];
            ull am[4] = { packbb(a4.x), packbb(a4.y), packbb(a4.z), packbb(a4.w) };
            ulonglong2 b0 = *(const ulonglong2*)&Xs[kk][tx * 8];
            ulonglong2 b1 = *(const ulonglong2*)&Xs[kk][tx * 8 + 4];
            ull bn[4] = { b0.x, b0.y, b1.x, b1.y };
            #pragma unroll
            for (int i = 0; i < 4; ++i)
                #pragma unroll
                for (int j = 0; j < 4; ++j)
                    acc[i][j] = fma2(am[i], bn[j], acc[i][j]);
        }
    }

    #pragma unroll
    for (int i = 0; i < 4; ++i) {
        const int m = m0 + ty * 4 + i;
        const float bv = bias[m];
        float r[8];
        #pragma unroll
        for (int j = 0; j < 4; ++j) {
            float2 f = unpack2(acc[i][j]);
            r[2*j]   = f.x + bv;
            r[2*j+1] = f.y + bv;
        }
        const size_t obase = ((size_t)b * M + m) * Nd + n0 + tx * 8;
        if (res) {
            float4 r0 = *(const float4*)(res + obase);
            float4 r1 = *(const float4*)(res + obase + 4);
            r[0] += r0.x; r[1] += r0.y; r[2] += r0.z; r[3] += r0.w;
            r[4] += r1.x; r[5] += r1.y; r[6] += r1.z; r[7] += r1.w;
        }
        *(float4*)(out + obase)     = make_float4(r[0], r[1], r[2], r[3]);
        *(float4*)(out + obase + 4) = make_float4(r[4], r[5], r[6], r[7]);
    }
}

// ---------------------------------------------------------------------------
// Kernel 3: flash attention, GEMM-style register tiling.
// Block = (b, h, 128-query tile); 256 threads (16x16).
// Thread owns S[4 keys][8 queries] then O[4 dh][8 queries] (FFMA2 pairs).
// SMEM: Q[64][128], K[64][64], V[64][64], S/P[64][128], stats.
// ---------------------------------------------------------------------------
#define ATTN_SMEM_FLOATS (64*128 + 64*64 + 64*64 + 64*128 + 3*128)
#define ATTN_SMEM_BYTES  (ATTN_SMEM_FLOATS * 4)

__global__ __launch_bounds__(256, 2)
void attn_kernel() {
    extern __shared__ __align__(16) float sm[];
    float* Qs = sm;                     // [64][128]
    float* Ks = Qs + 64*128;            // [64][64]
    float* Vs = Ks + 64*64;             // [64][64]
    float* Ss = Vs + 64*64;             // [64][128] scores -> P
    float* mS = Ss + 64*128;            // [128]
    float* lS = mS + 128;               // [128]
    float* aS = lS + 128;               // [128] alpha

    const int b = blockIdx.z, h = blockIdx.y;
    const int q0 = blockIdx.x * 128;
    const int tid = threadIdx.x;
    const int tx = tid & 15, ty = tid >> 4;

    const float* qb = g_qkv + ((size_t)b * 3 * CCH + (size_t)h * DH) * NPOS;
    const float* kb = qb + (size_t)CCH * NPOS;
    const float* vb = qb + (size_t)2 * CCH * NPOS;

    // Load Q tile (64 dh x 128 q), scale by dh^-0.5 = 0.125
    #pragma unroll
    for (int r = 0; r < 8; ++r) {
        int idx = r * 256 + tid;            // float4 index
        int c = idx >> 5, qq = (idx & 31) * 4;
        float4 v = *(const float4*)(qb + (size_t)c * NPOS + q0 + qq);
        v.x *= 0.125f; v.y *= 0.125f; v.z *= 0.125f; v.w *= 0.125f;
        *(float4*)&Qs[c * 128 + qq] = v;
    }
    if (tid < 128) { mS[tid] = -1e30f; lS[tid] = 0.f; }

    ull O[4][4];
    #pragma unroll
    for (int i = 0; i < 4; ++i)
        #pragma unroll
        for (int j = 0; j < 4; ++j) O[i][j] = 0ull;

    for (int jt = 0; jt < 16; ++jt) {
        const float* kt = kb + jt * 64;
        const float* vt = vb + jt * 64;
        __syncthreads();                    // protect prior Ks/Vs/Ss reads
        #pragma unroll
        for (int r = 0; r < 4; ++r) {
            int idx = r * 256 + tid;        // float4 index
            int c = idx >> 4, j = (idx & 15) * 4;
            *(float4*)&Ks[c * 64 + j] = *(const float4*)(kt + (size_t)c * NPOS + j);
            *(float4*)&Vs[c * 64 + j] = *(const float4*)(vt + (size_t)c * NPOS + j);
        }
        __syncthreads();

        // --- QK^T: S[4 keys][8 q] ---
        ull S[4][4];
        #pragma unroll
        for (int i = 0; i < 4; ++i)
            #pragma unroll
            for (int j = 0; j < 4; ++j) S[i][j] = 0ull;

        #pragma unroll 8
        for (int c = 0; c < 64; ++c) {
            float4 k4 = *(const float4*)&Ks[c * 64 + ty * 4];
            ull a0 = packbb(k4.x), a1 = packbb(k4.y);
            ull a2 = packbb(k4.z), a3 = packbb(k4.w);
            ulonglong2 q01 = *(const ulonglong2*)&Qs[c * 128 + tx * 8];
            ulonglong2 q23 = *(const ulonglong2*)&Qs[c * 128 + tx * 8 + 4];
            S[0][0] = fma2(a0, q01.x, S[0][0]); S[0][1] = fma2(a0, q01.y, S[0][1]);
            S[0][2] = fma2(a0, q23.x, S[0][2]); S[0][3] = fma2(a0, q23.y, S[0][3]);
            S[1][0] = fma2(a1, q01.x, S[1][0]); S[1][1] = fma2(a1, q01.y, S[1][1]);
            S[1][2] = fma2(a1, q23.x, S[1][2]); S[1][3] = fma2(a1, q23.y, S[1][3]);
            S[2][0] = fma2(a2, q01.x, S[2][0]); S[2][1] = fma2(a2, q01.y, S[2][1]);
            S[2][2] = fma2(a2, q23.x, S[2][2]); S[2][3] = fma2(a2, q23.y, S[2][3]);
            S[3][0] = fma2(a3, q01.x, S[3][0]); S[3][1] = fma2(a3, q01.y, S[3][1]);
            S[3][2] = fma2(a3, q23.x, S[3][2]); S[3][3] = fma2(a3, q23.y, S[3][3]);
        }
        // write S to SMEM
        #pragma unroll
        for (int i = 0; i < 4; ++i) {
            float2 f0 = unpack2(S[i][0]), f1 = unpack2(S[i][1]);
            float2 f2 = unpack2(S[i][2]), f3 = unpack2(S[i][3]);
            float* row = &Ss[(ty * 4 + i) * 128 + tx * 8];
            *(float4*)row       = make_float4(f0.x, f0.y, f1.x, f1.y);
            *(float4*)(row + 4) = make_float4(f2.x, f2.y, f3.x, f3.y);
        }
        __syncthreads();

        // --- online softmax over this key tile (one thread per query) ---
        if (tid < 128) {
            float m = mS[tid];
            float mold = m;
            #pragma unroll 8
            for (int j = 0; j < 64; ++j) m = fmaxf(m, Ss[j * 128 + tid]);
            float alpha = __expf(mold - m);
            float ssum = 0.f;
            #pragma unroll 8
            for (int j = 0; j < 64; ++j) {
                float e = __expf(Ss[j * 128 + tid] - m);
                Ss[j * 128 + tid] = e;
                ssum += e;
            }
            mS[tid] = m;
            lS[tid] = lS[tid] * alpha + ssum;
            aS[tid] = alpha;
        }
        __syncthreads();

        // --- rescale O by alpha (per query) ---
        float4 al0 = *(const float4*)&aS[tx * 8];
        float4 al1 = *(const float4*)&aS[tx * 8 + 4];
        ull a2v[4] = { pack2(al0.x, al0.y), pack2(al0.z, al0.w),
                       pack2(al1.x, al1.y), pack2(al1.z, al1.w) };
        #pragma unroll
        for (int i = 0; i < 4; ++i)
            #pragma unroll
            for (int j4 = 0; j4 < 4; ++j4)
                O[i][j4] = mul2(O[i][j4], a2v[j4]);

        // --- O += V @ P ---
        #pragma unroll 8
        for (int j = 0; j < 64; ++j) {
            float v0 = Vs[(ty * 4 + 0) * 64 + j];
            float v1 = Vs[(ty * 4 + 1) * 64 + j];
            float v2 = Vs[(ty * 4 + 2) * 64 + j];
            float v3 = Vs[(ty * 4 + 3) * 64 + j];
            ull w0 = packbb(v0), w1 = packbb(v1), w2 = packbb(v2), w3 = packbb(v3);
            ulonglong2 p01 = *(const ulonglong2*)&Ss[j * 128 + tx * 8];
            ulonglong2 p23 = *(const ulonglong2*)&Ss[j * 128 + tx * 8 + 4];
            O[0][0] = fma2(w0, p01.x, O[0][0]); O[0][1] = fma2(w0, p01.y, O[0][1]);
            O[0][2] = fma2(w0, p23.x, O[0][2]); O[0][3] = fma2(w0, p23.y, O[0][3]);
            O[1][0] = fma2(w1, p01.x, O[1][0]); O[1][1] = fma2(w1, p01.y, O[1][1]);
            O[1][2] = fma2(w1, p23.x, O[1][2]); O[1][3] = fma2(w1, p23.y, O[1][3]);
            O[2][0] = fma2(w2, p01.x, O[2][0]); O[2][1] = fma2(w2, p01.y, O[2][1]);
            O[2][2] = fma2(w2, p23.x, O[2][2]); O[2][3] = fma2(w2, p23.y, O[2][3]);
            O[3][0] = fma2(w3, p01.x, O[3][0]); O[3][1] = fma2(w3, p01.y, O[3][1]);
            O[3][2] = fma2(w3, p23.x, O[3][2]); O[3][3] = fma2(w3, p23.y, O[3][3]);
        }
    }

    // epilogue: normalize by 1/l and store
    float rl[8];
    #pragma unroll
    for (int j = 0; j < 8; ++j) rl[j] = 1.f / lS[tx * 8 + j];
    float* ob = g_o + ((size_t)b * CCH + (size_t)h * DH) * NPOS + q0;
    #pragma unroll
    for (int i = 0; i < 4; ++i) {
        float2 f0 = unpack2(O[i][0]), f1 = unpack2(O[i][1]);
        float2 f2 = unpack2(O[i][2]), f3 = unpack2(O[i][3]);
        float* row = ob + (size_t)(ty * 4 + i) * NPOS + tx * 8;
        *(float4*)row       = make_float4(f0.x * rl[0], f0.y * rl[1], f1.x * rl[2], f1.y * rl[3]);
        *(float4*)(row + 4) = make_float4(f2.x * rl[4], f2.y * rl[5], f3.x * rl[6], f3.y * rl[7]);
    }
}

// ---------------------------------------------------------------------------
// Launch
// ---------------------------------------------------------------------------
extern "C" void kernel_launch(void* const* d_in, const int* in_sizes, int n_in,
                              void* d_out, int out_size) {
    const float* x        = (const float*)d_in[0];
    const float* n_weight = (const float*)d_in[1];
    const float* n_bias   = (const float*)d_in[2];
    const float* qkv_w    = (const float*)d_in[3];
    const float* qkv_b    = (const float*)d_in[4];
    const float* p_w      = (const float*)d_in[5];
    const float* p_b      = (const float*)d_in[6];
    float* out = (float*)d_out;

    static int smem_set = 0;
    if (!smem_set) {
        cudaFuncSetAttribute(attn_kernel,
                             cudaFuncAttributeMaxDynamicSharedMemorySize,
                             ATTN_SMEM_BYTES);
        smem_set = 1;
    }

    // 1) GroupNorm -> g_xn
    gn_kernel<<<BATCH * GRP, 256>>>(x, n_weight, n_bias);

    // 2) QKV GEMM: g_qkv = qkv_w @ g_xn + qkv_b   (M=768)
    gemm_kernel<<<dim3(8, 12, BATCH), 256>>>(qkv_w, qkv_b, nullptr, nullptr, 768, 0);

    // 3) Attention: g_qkv -> g_o
    attn_kernel<<<dim3(8, NH, BATCH), 256, ATTN_SMEM_BYTES>>>();

    // 4) Proj + bias + residual: out = x + p_w @ g_o + p_b   (M=256)
    gemm_kernel<<<dim3(8, 4, BATCH), 256>>>(p_w, p_b, x, out, 256, 1);
}